// round 1
// baseline (speedup 1.0000x reference)
#include <cuda_runtime.h>
#include <math.h>

#define B_  8
#define L_  4096
#define D_  512
#define M_TOTAL (B_ * L_)

// ---------------- scratch (no allocations allowed) ----------------
__device__ int g_seg_start[B_ * L_];
__device__ int g_seg_cnt[B_ * L_];

// ---------------- Kernel 1: fused logits GEMM -----------------
// masked_probs[b,t] = valid(t) * sigmoid( gelu(X[b,t,:]@W1 + b1) @ W2 + b2 )
// BM=128 rows/block, loop N in 8 chunks of 64, K-tiles of 16.
#define BM 128
#define BN 64
#define BK 16

__global__ __launch_bounds__(256, 4)
void gemm_logits_kernel(const float* __restrict__ X,
                        const float* __restrict__ W1,
                        const float* __restrict__ b1,
                        const float* __restrict__ W2,
                        const float* __restrict__ b2,
                        const float* __restrict__ lengths,
                        float* __restrict__ out_masked)
{
    __shared__ float As[BK][BM + 4];   // transposed: As[k][m]
    __shared__ float Bs[BK][BN];
    __shared__ float s_logit[BM];

    const int tid = threadIdx.x;
    const int tx = tid & 15;           // 0..15  -> N
    const int ty = tid >> 4;           // 0..15  -> M
    const int m0 = blockIdx.x * BM;

    for (int i = tid; i < BM; i += 256) s_logit[i] = 0.0f;
    __syncthreads();

    for (int nc = 0; nc < 8; ++nc) {
        const int n0 = nc * BN;

        float acc[8][4];
#pragma unroll
        for (int i = 0; i < 8; ++i)
#pragma unroll
            for (int j = 0; j < 4; ++j) acc[i][j] = 0.0f;

        for (int k0 = 0; k0 < D_; k0 += BK) {
            // load A tile (128x16) transposed into As[k][m]
#pragma unroll
            for (int l = 0; l < 2; ++l) {
                int idx = tid + l * 256;       // 0..511
                int m = idx >> 2;              // 0..127
                int c = idx & 3;               // 0..3 (groups of 4 k)
                float4 v = *(const float4*)(X + (size_t)(m0 + m) * D_ + k0 + c * 4);
                As[c * 4 + 0][m] = v.x;
                As[c * 4 + 1][m] = v.y;
                As[c * 4 + 2][m] = v.z;
                As[c * 4 + 3][m] = v.w;
            }
            // load B tile (16x64)
            {
                int r  = tid >> 4;             // 0..15
                int cg = tid & 15;             // 0..15
                float4 v = *(const float4*)(W1 + (size_t)(k0 + r) * D_ + n0 + cg * 4);
                *(float4*)&Bs[r][cg * 4] = v;
            }
            __syncthreads();

#pragma unroll
            for (int kk = 0; kk < BK; ++kk) {
                float4 a0 = *(const float4*)&As[kk][ty * 8];
                float4 a1 = *(const float4*)&As[kk][ty * 8 + 4];
                float4 bb = *(const float4*)&Bs[kk][tx * 4];
                float a[8] = {a0.x, a0.y, a0.z, a0.w, a1.x, a1.y, a1.z, a1.w};
                float bv[4] = {bb.x, bb.y, bb.z, bb.w};
#pragma unroll
                for (int i = 0; i < 8; ++i)
#pragma unroll
                    for (int j = 0; j < 4; ++j)
                        acc[i][j] = fmaf(a[i], bv[j], acc[i][j]);
            }
            __syncthreads();
        }

        // epilogue for this N-chunk: gelu + dot with W2
        float w2v[4], b1v[4];
#pragma unroll
        for (int j = 0; j < 4; ++j) {
            int col = n0 + tx * 4 + j;
            w2v[j] = W2[col];
            b1v[j] = b1[col];
        }
#pragma unroll
        for (int i = 0; i < 8; ++i) {
            float p = 0.0f;
#pragma unroll
            for (int j = 0; j < 4; ++j) {
                float hx = acc[i][j] + b1v[j];
                float g = 0.5f * hx * (1.0f + erff(hx * 0.7071067811865476f)); // exact gelu
                p = fmaf(g, w2v[j], p);
            }
            // reduce across the 16 tx lanes (half-warp segments)
#pragma unroll
            for (int off = 8; off > 0; off >>= 1)
                p += __shfl_down_sync(0xffffffffu, p, off, 16);
            if (tx == 0) s_logit[ty * 8 + i] += p;
        }
        __syncthreads();
    }

    if (tid < BM) {
        int grow = m0 + tid;                // row in [0, 32768)
        float lg = s_logit[tid] + b2[0];
        float prob = 1.0f / (1.0f + expf(-lg));
        int b = grow >> 12;                 // /4096
        int t = grow & (L_ - 1);
        int alen = (int)(lengths[b] * (float)L_);
        out_masked[grow] = (t < alen) ? prob : 0.0f;
    }
}

// ---------------- Kernel 2: boundaries, cumsum, segment table ----------------
__global__ __launch_bounds__(512)
void seg_kernel(const float* __restrict__ masked,
                const float* __restrict__ lengths,
                int S,
                float* __restrict__ out_short,
                float* __restrict__ out_nb)
{
    const int b = blockIdx.x;
    const int tid = threadIdx.x;          // 512 threads, 8 elems each
    __shared__ int s_wsum[16];
    __shared__ int s_end[L_];

    const int alen = (int)(lengths[b] * (float)L_);
    int last = alen - 1;
    if (last < 0) last = 0;
    if (last > L_ - 1) last = L_ - 1;

    const int base = tid * 8;
    int h[8];
    int loc = 0;
#pragma unroll
    for (int i = 0; i < 8; ++i) {
        int t = base + i;
        float p = masked[(size_t)b * L_ + t];   // masked==0 beyond valid
        int hv = (p > 0.5f) ? 1 : 0;
        if (t == last) hv = 1;                  // forced boundary at last valid pos
        h[i] = hv;
        loc += hv;
    }

    // block inclusive scan over per-thread totals
    const int lane = tid & 31, wid = tid >> 5;
    int sc = loc;
#pragma unroll
    for (int off = 1; off < 32; off <<= 1) {
        int n = __shfl_up_sync(0xffffffffu, sc, off);
        if (lane >= off) sc += n;
    }
    if (lane == 31) s_wsum[wid] = sc;
    __syncthreads();
    if (wid == 0) {
        int w = (lane < 16) ? s_wsum[lane] : 0;
#pragma unroll
        for (int off = 1; off < 16; off <<= 1) {
            int n = __shfl_up_sync(0xffffffffu, w, off);
            if (lane >= off) w += n;
        }
        if (lane < 16) s_wsum[lane] = w;        // inclusive warp sums
    }
    __syncthreads();

    const int warp_off = (wid == 0) ? 0 : s_wsum[wid - 1];
    const int excl = warp_off + (sc - loc);     // boundaries strictly before this thread
    const int nb = s_wsum[15];                  // total boundaries for row b (>=1)

    int run = excl;
#pragma unroll
    for (int i = 0; i < 8; ++i) {
        if (h[i]) s_end[run] = base + i;        // seg 'run' ends at t
        run += h[i];
    }
    __syncthreads();

    // fill start/cnt for all S segments
    for (int s = tid; s < S; s += 512) {
        int st, en;
        if (s < nb) {
            en = s_end[s];
            st = (s == 0) ? 0 : (s_end[s - 1] + 1);
        } else if (s == nb) {
            // reference quirk: invalid tail positions have hh1 == nb
            st = s_end[nb - 1] + 1;
            en = L_ - 1;
        } else {
            st = 0; en = -1;
        }
        g_seg_start[b * L_ + s] = st;
        g_seg_cnt[b * L_ + s] = en - st + 1;
    }

    if (tid == 0) {
        out_nb[b] = (float)nb;
        int sm = (S > 1) ? S : 1;
        out_short[b] = (float)nb / (float)sm;
    }
}

// ---------------- Kernel 3: segment mean-pool ----------------
__global__ __launch_bounds__(128)
void pool_kernel(const float* __restrict__ hidden, int S, float* __restrict__ out_pooled)
{
    const int s = blockIdx.x;
    const int b = blockIdx.y;
    const int tid = threadIdx.x;             // 128 threads x float4 = 512 floats

    const int st  = g_seg_start[b * L_ + s];
    const int cnt = g_seg_cnt[b * L_ + s];

    const float4* base = (const float4*)(hidden + (size_t)b * L_ * D_);
    float4 acc = make_float4(0.f, 0.f, 0.f, 0.f);
    for (int r = 0; r < cnt; ++r) {
        float4 v = base[(size_t)(st + r) * (D_ / 4) + tid];
        acc.x += v.x; acc.y += v.y; acc.z += v.z; acc.w += v.w;
    }
    float inv = 1.0f / ((float)cnt + 1e-9f);  // cnt==0 -> acc==0 -> zeros
    acc.x *= inv; acc.y *= inv; acc.z *= inv; acc.w *= inv;

    ((float4*)out_pooled)[((size_t)b * S + s) * (D_ / 4) + tid] = acc;
}

// ---------------- launch ----------------
extern "C" void kernel_launch(void* const* d_in, const int* in_sizes, int n_in,
                              void* d_out, int out_size)
{
    const float* hidden  = (const float*)d_in[0];
    const float* lengths = (const float*)d_in[1];
    const float* W1      = (const float*)d_in[2];
    const float* b1      = (const float*)d_in[3];
    const float* W2      = (const float*)d_in[4];
    const float* b2      = (const float*)d_in[5];
    float* out = (float*)d_out;

    // out layout: pooled [B,S,D] | masked_probs [B,L] | shortened [B] | num_boundaries [B]
    int S = (out_size - B_ * L_ - 2 * B_) / (B_ * D_);
    if (S < 1) S = 1;

    float* out_pooled = out;
    float* out_masked = out + (size_t)B_ * S * D_;
    float* out_short  = out_masked + (size_t)B_ * L_;
    float* out_nb     = out_short + B_;

    gemm_logits_kernel<<<M_TOTAL / BM, 256>>>(hidden, W1, b1, W2, b2, lengths, out_masked);
    seg_kernel<<<B_, 512>>>(out_masked, lengths, S, out_short, out_nb);
    pool_kernel<<<dim3(S, B_), 128>>>(hidden, S, out_pooled);
}

// round 3
// speedup vs baseline: 1.4639x; 1.4639x over previous
#include <cuda_runtime.h>
#include <cuda_bf16.h>
#include <math.h>
#include <stdint.h>

#define B_  8
#define L_  4096
#define D_  512
#define M_TOTAL (B_ * L_)

// ------------------------------------------------------------------
// device scratch (module-static, no runtime allocation)
// ------------------------------------------------------------------
__device__ __nv_bfloat16 g_xs[3][(size_t)M_TOTAL * D_];  // X splits, row-major [m][k]
__device__ __nv_bfloat16 g_w1t[3][D_ * D_];              // W1^T splits [n][k]
__device__ float g_part[4][M_TOTAL];                     // per-n-tile partial logits
__device__ int g_seg_start[B_ * L_];
__device__ int g_seg_cnt[B_ * L_];

// ------------------------------------------------------------------
// PTX helpers (all plain sm_80-level — compile for compute_103)
// ------------------------------------------------------------------
__device__ __forceinline__ uint32_t smem_u32(const void* p) {
    uint32_t a;
    asm("{ .reg .u64 t; cvta.to.shared.u64 t, %1; cvt.u32.u64 %0, t; }" : "=r"(a) : "l"(p));
    return a;
}
#define CP_ASYNC16(dst, src) \
    asm volatile("cp.async.cg.shared.global [%0], [%1], 16;" :: "r"(dst), "l"(src))
#define CP_COMMIT() asm volatile("cp.async.commit_group;")
#define CP_WAIT(n)  asm volatile("cp.async.wait_group %0;" :: "n"(n))

__device__ __forceinline__ void ldsm4(uint32_t* r, uint32_t a) {
    asm volatile("ldmatrix.sync.aligned.m8n8.x4.shared.b16 {%0,%1,%2,%3}, [%4];"
                 : "=r"(r[0]), "=r"(r[1]), "=r"(r[2]), "=r"(r[3]) : "r"(a));
}
__device__ __forceinline__ void mma_bf16(float* c, const uint32_t* a, const uint32_t* b) {
    asm volatile(
        "mma.sync.aligned.m16n8k16.row.col.f32.bf16.bf16.f32 "
        "{%0,%1,%2,%3}, {%4,%5,%6,%7}, {%8,%9}, {%0,%1,%2,%3};"
        : "+f"(c[0]), "+f"(c[1]), "+f"(c[2]), "+f"(c[3])
        : "r"(a[0]), "r"(a[1]), "r"(a[2]), "r"(a[3]), "r"(b[0]), "r"(b[1]));
}

// exact 3-way bf16 split of fp32
__device__ __forceinline__ void split3(float x, uint16_t& h, uint16_t& m, uint16_t& l) {
    __nv_bfloat16 bh = __float2bfloat16_rn(x);
    float r = x - __bfloat162float(bh);
    __nv_bfloat16 bm = __float2bfloat16_rn(r);
    float r2 = r - __bfloat162float(bm);
    __nv_bfloat16 bl = __float2bfloat16_rn(r2);
    h = reinterpret_cast<uint16_t&>(bh);
    m = reinterpret_cast<uint16_t&>(bm);
    l = reinterpret_cast<uint16_t&>(bl);
}

// ------------------------------------------------------------------
// Kernel A: split X -> 3 bf16 planes
// ------------------------------------------------------------------
__global__ __launch_bounds__(256)
void xsplit_kernel(const float* __restrict__ X) {
    size_t i = (size_t)blockIdx.x * 256 + threadIdx.x;   // float4 index
    float4 v = ((const float4*)X)[i];
    uint16_t h[4], m[4], l[4];
    split3(v.x, h[0], m[0], l[0]);
    split3(v.y, h[1], m[1], l[1]);
    split3(v.z, h[2], m[2], l[2]);
    split3(v.w, h[3], m[3], l[3]);
    ((uint2*)g_xs[0])[i] = make_uint2((uint32_t)h[0] | ((uint32_t)h[1] << 16),
                                      (uint32_t)h[2] | ((uint32_t)h[3] << 16));
    ((uint2*)g_xs[1])[i] = make_uint2((uint32_t)m[0] | ((uint32_t)m[1] << 16),
                                      (uint32_t)m[2] | ((uint32_t)m[3] << 16));
    ((uint2*)g_xs[2])[i] = make_uint2((uint32_t)l[0] | ((uint32_t)l[1] << 16),
                                      (uint32_t)l[2] | ((uint32_t)l[3] << 16));
}

// ------------------------------------------------------------------
// Kernel B: W1 -> transposed bf16 splits
// ------------------------------------------------------------------
__global__ __launch_bounds__(512)
void w1split_kernel(const float* __restrict__ W1) {
    int k = blockIdx.x;
    int n = threadIdx.x;
    float w = W1[k * D_ + n];
    uint16_t h, m, l;
    split3(w, h, m, l);
    g_w1t[0][n * D_ + k] = reinterpret_cast<__nv_bfloat16&>(h);
    g_w1t[1][n * D_ + k] = reinterpret_cast<__nv_bfloat16&>(m);
    g_w1t[2][n * D_ + k] = reinterpret_cast<__nv_bfloat16&>(l);
}

// ------------------------------------------------------------------
// Kernel C: mma.sync bf16 GEMM, 6 split-products, fused gelu/W2 epilogue
// BM=128, BN=128, BK=32, 256 threads (8 warps, warp tile 64x32)
// ------------------------------------------------------------------
#define ROWB 80                    // bytes per smem row (40 bf16, conflict-free ldmatrix)
#define SPLIT_TILE (128 * ROWB)    // 10240 B
#define BUF_SIDE (3 * SPLIT_TILE)  // 30720 B
#define OFF_B (2 * BUF_SIDE)       // Bs after As[2]
#define OFF_B1 (4 * BUF_SIDE)      // 122880
#define OFF_W2 (OFF_B1 + 512)
#define OFF_PART (OFF_W2 + 512)
#define SMEM_DYN (OFF_PART + 4 * 128 * 4)   // 125952
#define NCHUNK (D_ / 32)

__global__ __launch_bounds__(256, 1)
void gemm_mma_kernel(const float* __restrict__ b1, const float* __restrict__ W2)
{
    extern __shared__ char smem[];
    const uint32_t sb = smem_u32(smem);
    const int tid = threadIdx.x;
    const int wid = tid >> 5;
    const int lane = tid & 31;
    const int warp_m = wid >> 2;         // 0..1 -> 64 rows
    const int warp_n = wid & 3;          // 0..3 -> 32 cols
    const int quad = lane & 3;
    const int rowq = lane >> 2;

    const int m0 = (blockIdx.x >> 2) * 128;
    const int nt = blockIdx.x & 3;
    const int n0 = nt * 128;

    float* s_b1 = (float*)(smem + OFF_B1);
    float* s_w2 = (float*)(smem + OFF_W2);
    float* s_part = (float*)(smem + OFF_PART);

    if (tid < 128) { s_b1[tid] = b1[n0 + tid]; s_w2[tid] = W2[n0 + tid]; }

    float acc[4][4][4];
#pragma unroll
    for (int i = 0; i < 4; ++i)
#pragma unroll
        for (int j = 0; j < 4; ++j)
#pragma unroll
            for (int k = 0; k < 4; ++k) acc[i][j][k] = 0.0f;

    // per-lane ldmatrix address components
    const int l8 = lane & 7, sel = lane >> 3;
    const uint32_t a_row_off = (uint32_t)((l8 + (sel & 1) * 8) * ROWB + (sel >> 1) * 16);
    const uint32_t b_row_off = (uint32_t)((l8 + (sel >> 1) * 8) * ROWB + (sel & 1) * 16);

    // chunk loader: 1536 x 16B per side
    auto load_chunk = [&](int c) {
        const int buf = c & 1;
        const int k0 = c * 32;
        const uint32_t da = sb + buf * BUF_SIDE;
        const uint32_t db = sb + OFF_B + buf * BUF_SIDE;
#pragma unroll
        for (int it = 0; it < 6; ++it) {
            int i = tid + it * 256;
            int s = i >> 9;
            int r = (i >> 2) & 127;
            int j = i & 3;
            uint32_t doff = (uint32_t)(s * SPLIT_TILE + r * ROWB + j * 16);
            CP_ASYNC16(da + doff, &g_xs[s][(size_t)(m0 + r) * D_ + k0 + j * 8]);
            CP_ASYNC16(db + doff, &g_w1t[s][(size_t)(n0 + r) * D_ + k0 + j * 8]);
        }
        CP_COMMIT();
    };

    load_chunk(0);

    const int ca[6] = {0, 0, 1, 0, 1, 2};
    const int cb[6] = {0, 1, 0, 2, 1, 0};

    for (int c = 0; c < NCHUNK; ++c) {
        if (c + 1 < NCHUNK) { load_chunk(c + 1); CP_WAIT(1); }
        else { CP_WAIT(0); }
        __syncthreads();

        const int buf = c & 1;
        const uint32_t sa_base = sb + buf * BUF_SIDE + (warp_m * 64) * ROWB + a_row_off;
        const uint32_t sbb_base = sb + OFF_B + buf * BUF_SIDE + (warp_n * 32) * ROWB + b_row_off;

#pragma unroll
        for (int k16 = 0; k16 < 2; ++k16) {
            uint32_t afr[3][16], bfr[3][8];
#pragma unroll
            for (int s = 0; s < 3; ++s) {
#pragma unroll
                for (int mi = 0; mi < 4; ++mi)
                    ldsm4(&afr[s][mi * 4],
                          sa_base + (uint32_t)(s * SPLIT_TILE + mi * 16 * ROWB + k16 * 32));
#pragma unroll
                for (int nj = 0; nj < 2; ++nj)
                    ldsm4(&bfr[s][nj * 4],
                          sbb_base + (uint32_t)(s * SPLIT_TILE + nj * 16 * ROWB + k16 * 32));
            }
#pragma unroll
            for (int q = 0; q < 6; ++q) {
                const uint32_t* A = afr[ca[q]];
                const uint32_t* Bf = bfr[cb[q]];
#pragma unroll
                for (int mi = 0; mi < 4; ++mi)
#pragma unroll
                    for (int ni = 0; ni < 4; ++ni)
                        mma_bf16(acc[mi][ni], &A[mi * 4],
                                 &Bf[(ni >> 1) * 4 + (ni & 1) * 2]);
            }
        }
        __syncthreads();
    }

    // ---- epilogue: gelu + dot(W2) partial per row ----
#pragma unroll
    for (int mi = 0; mi < 4; ++mi) {
#pragma unroll
        for (int h = 0; h < 2; ++h) {
            float p = 0.0f;
#pragma unroll
            for (int ni = 0; ni < 4; ++ni) {
#pragma unroll
                for (int cbit = 0; cbit < 2; ++cbit) {
                    int nloc = warp_n * 32 + ni * 8 + quad * 2 + cbit;
                    float v = acc[mi][ni][h * 2 + cbit] + s_b1[nloc];
                    float g = 0.5f * v * (1.0f + erff(v * 0.7071067811865476f));
                    p = fmaf(g, s_w2[nloc], p);
                }
            }
            p += __shfl_xor_sync(0xffffffffu, p, 1);
            p += __shfl_xor_sync(0xffffffffu, p, 2);
            if (quad == 0)
                s_part[warp_n * 128 + warp_m * 64 + mi * 16 + h * 8 + rowq] = p;
        }
    }
    __syncthreads();
    if (tid < 128) {
        float r = s_part[tid] + s_part[128 + tid] + s_part[256 + tid] + s_part[384 + tid];
        g_part[nt][m0 + tid] = r;
    }
}

// ------------------------------------------------------------------
// Kernel D: reduce partials -> probs -> boundaries -> segment table
// ------------------------------------------------------------------
__global__ __launch_bounds__(512)
void seg_kernel(const float* __restrict__ lengths,
                const float* __restrict__ b2,
                int S,
                float* __restrict__ out_masked,
                float* __restrict__ out_short,
                float* __restrict__ out_nb)
{
    const int b = blockIdx.x;
    const int tid = threadIdx.x;
    __shared__ int s_wsum[16];
    __shared__ int s_end[L_];

    const int alen = (int)(lengths[b] * (float)L_);
    int last = alen - 1;
    if (last < 0) last = 0;
    if (last > L_ - 1) last = L_ - 1;

    const float b2v = b2[0];
    const int base = tid * 8;
    int h[8];
    int loc = 0;
#pragma unroll
    for (int i = 0; i < 8; ++i) {
        int t = base + i;
        int gm = b * L_ + t;
        float lg = g_part[0][gm] + g_part[1][gm] + g_part[2][gm] + g_part[3][gm] + b2v;
        float prob = 1.0f / (1.0f + expf(-lg));
        int valid = (t < alen) ? 1 : 0;
        out_masked[gm] = valid ? prob : 0.0f;
        int hv = (valid && prob > 0.5f) ? 1 : 0;
        if (t == last) hv = 1;
        h[i] = hv;
        loc += hv;
    }

    const int lane = tid & 31, wid = tid >> 5;
    int sc = loc;
#pragma unroll
    for (int off = 1; off < 32; off <<= 1) {
        int n = __shfl_up_sync(0xffffffffu, sc, off);
        if (lane >= off) sc += n;
    }
    if (lane == 31) s_wsum[wid] = sc;
    __syncthreads();
    if (wid == 0) {
        int w = (lane < 16) ? s_wsum[lane] : 0;
#pragma unroll
        for (int off = 1; off < 16; off <<= 1) {
            int n = __shfl_up_sync(0xffffffffu, w, off);
            if (lane >= off) w += n;
        }
        if (lane < 16) s_wsum[lane] = w;
    }
    __syncthreads();

    const int warp_off = (wid == 0) ? 0 : s_wsum[wid - 1];
    const int excl = warp_off + (sc - loc);
    const int nb = s_wsum[15];

    int run = excl;
#pragma unroll
    for (int i = 0; i < 8; ++i) {
        if (h[i]) s_end[run] = base + i;
        run += h[i];
    }
    __syncthreads();

    for (int s = tid; s < S; s += 512) {
        int st, en;
        if (s < nb) {
            en = s_end[s];
            st = (s == 0) ? 0 : (s_end[s - 1] + 1);
        } else if (s == nb) {
            st = s_end[nb - 1] + 1;   // reference quirk: invalid tail pools here
            en = L_ - 1;
        } else {
            st = 0; en = -1;
        }
        g_seg_start[b * L_ + s] = st;
        g_seg_cnt[b * L_ + s] = en - st + 1;
    }

    if (tid == 0) {
        out_nb[b] = (float)nb;
        int sm = (S > 1) ? S : 1;
        out_short[b] = (float)nb / (float)sm;
    }
}

// ------------------------------------------------------------------
// Kernel E: segment mean-pool, 4-row-parallel
// ------------------------------------------------------------------
__global__ __launch_bounds__(512)
void pool_kernel(const float* __restrict__ hidden, int S, float* __restrict__ out_pooled)
{
    const int s = blockIdx.x;
    const int b = blockIdx.y;
    const int tid = threadIdx.x;
    const int col = tid & 127;
    const int rg = tid >> 7;

    __shared__ float4 s_acc[512];

    const int st  = g_seg_start[b * L_ + s];
    const int cnt = g_seg_cnt[b * L_ + s];

    const float4* base = (const float4*)(hidden + (size_t)b * L_ * D_);
    float4 acc = make_float4(0.f, 0.f, 0.f, 0.f);
    for (int r = st + rg; r < st + cnt; r += 4) {
        float4 v = base[(size_t)r * (D_ / 4) + col];
        acc.x += v.x; acc.y += v.y; acc.z += v.z; acc.w += v.w;
    }
    s_acc[tid] = acc;
    __syncthreads();

    if (tid < 128) {
        float4 a = s_acc[tid], c2 = s_acc[tid + 128], c3 = s_acc[tid + 256], c4 = s_acc[tid + 384];
        a.x += c2.x + c3.x + c4.x;
        a.y += c2.y + c3.y + c4.y;
        a.z += c2.z + c3.z + c4.z;
        a.w += c2.w + c3.w + c4.w;
        float inv = 1.0f / ((float)cnt + 1e-9f);
        a.x *= inv; a.y *= inv; a.z *= inv; a.w *= inv;
        ((float4*)out_pooled)[((size_t)b * S + s) * (D_ / 4) + tid] = a;
    }
}

// ------------------------------------------------------------------
extern "C" void kernel_launch(void* const* d_in, const int* in_sizes, int n_in,
                              void* d_out, int out_size)
{
    const float* hidden  = (const float*)d_in[0];
    const float* lengths = (const float*)d_in[1];
    const float* W1      = (const float*)d_in[2];
    const float* b1      = (const float*)d_in[3];
    const float* W2      = (const float*)d_in[4];
    const float* b2      = (const float*)d_in[5];
    float* out = (float*)d_out;

    int S = (out_size - B_ * L_ - 2 * B_) / (B_ * D_);
    if (S < 1) S = 1;

    float* out_pooled = out;
    float* out_masked = out + (size_t)B_ * S * D_;
    float* out_short  = out_masked + (size_t)B_ * L_;
    float* out_nb     = out_short + B_;

    cudaFuncSetAttribute(gemm_mma_kernel, cudaFuncAttributeMaxDynamicSharedMemorySize, SMEM_DYN);

    xsplit_kernel<<<(M_TOTAL * D_ / 4) / 256, 256>>>(hidden);
    w1split_kernel<<<D_, 512>>>(W1);
    gemm_mma_kernel<<<(M_TOTAL / 128) * 4, 256, SMEM_DYN>>>(b1, W2);
    seg_kernel<<<B_, 512>>>(lengths, b2, S, out_masked, out_short, out_nb);
    pool_kernel<<<dim3(S, B_), 512>>>(hidden, S, out_pooled);
}

// round 4
// speedup vs baseline: 5.4149x; 3.6991x over previous
#include <cuda_runtime.h>
#include <cuda_fp16.h>
#include <math.h>
#include <stdint.h>

#define B_  8
#define L_  4096
#define D_  512
#define M_TOTAL (B_ * L_)
#define WSCALE 256.0f
#define INV_WSCALE 0.00390625f

// ------------------------------------------------------------------
// device scratch (module-static, no runtime allocation)
// ------------------------------------------------------------------
__device__ __half g_xs[2][(size_t)M_TOTAL * D_];   // X splits [m][k]
__device__ __half g_w1t[2][D_ * D_];               // (W1*256)^T splits [n][k]
__device__ float g_part[4][M_TOTAL];               // per-n-tile partial logits
__device__ int g_seg_start[B_ * L_];
__device__ int g_seg_cnt[B_ * L_];
__device__ int g_nb[B_];
__device__ float g_tailpart[B_][16][D_];

// ------------------------------------------------------------------
// PTX helpers (sm_80-level, safe for compute_103 non-a)
// ------------------------------------------------------------------
__device__ __forceinline__ uint32_t smem_u32(const void* p) {
    uint32_t a;
    asm("{ .reg .u64 t; cvta.to.shared.u64 t, %1; cvt.u32.u64 %0, t; }" : "=r"(a) : "l"(p));
    return a;
}
#define CP_ASYNC16(dst, src) \
    asm volatile("cp.async.cg.shared.global [%0], [%1], 16;" :: "r"(dst), "l"(src))
#define CP_COMMIT() asm volatile("cp.async.commit_group;")
#define CP_WAIT(n)  asm volatile("cp.async.wait_group %0;" :: "n"(n))

__device__ __forceinline__ void ldsm4(uint32_t* r, uint32_t a) {
    asm volatile("ldmatrix.sync.aligned.m8n8.x4.shared.b16 {%0,%1,%2,%3}, [%4];"
                 : "=r"(r[0]), "=r"(r[1]), "=r"(r[2]), "=r"(r[3]) : "r"(a));
}
__device__ __forceinline__ void mma_f16(float* c, const uint32_t* a, const uint32_t* b) {
    asm volatile(
        "mma.sync.aligned.m16n8k16.row.col.f32.f16.f16.f32 "
        "{%0,%1,%2,%3}, {%4,%5,%6,%7}, {%8,%9}, {%0,%1,%2,%3};"
        : "+f"(c[0]), "+f"(c[1]), "+f"(c[2]), "+f"(c[3])
        : "r"(a[0]), "r"(a[1]), "r"(a[2]), "r"(a[3]), "r"(b[0]), "r"(b[1]));
}

// exact 2-way fp16 split of fp32 (residual ~2^-22 relative)
__device__ __forceinline__ void split2(float x, uint16_t& h, uint16_t& m) {
    __half hh = __float2half_rn(x);
    float r = x - __half2float(hh);
    __half hm = __float2half_rn(r);
    h = reinterpret_cast<uint16_t&>(hh);
    m = reinterpret_cast<uint16_t&>(hm);
}

// ------------------------------------------------------------------
// Kernel A: split X -> 2 fp16 planes (skip invalid rows)
// ------------------------------------------------------------------
__global__ __launch_bounds__(256)
void xsplit_kernel(const float* __restrict__ X, const float* __restrict__ lengths) {
    size_t i = (size_t)blockIdx.x * 256 + threadIdx.x;   // float4 index
    int m = (int)(i >> 7);                                // row (D/4 = 128)
    int b = m >> 12;
    int t = m & (L_ - 1);
    int alen = (int)(lengths[b] * (float)L_);
    if (t >= alen) return;                                // row never used

    float4 v = ((const float4*)X)[i];
    uint16_t h[4], mm[4];
    split2(v.x, h[0], mm[0]);
    split2(v.y, h[1], mm[1]);
    split2(v.z, h[2], mm[2]);
    split2(v.w, h[3], mm[3]);
    ((uint2*)g_xs[0])[i] = make_uint2((uint32_t)h[0] | ((uint32_t)h[1] << 16),
                                      (uint32_t)h[2] | ((uint32_t)h[3] << 16));
    ((uint2*)g_xs[1])[i] = make_uint2((uint32_t)mm[0] | ((uint32_t)mm[1] << 16),
                                      (uint32_t)mm[2] | ((uint32_t)mm[3] << 16));
}

// ------------------------------------------------------------------
// Kernel B: W1 -> transposed, scaled (x256) fp16 splits
// ------------------------------------------------------------------
__global__ __launch_bounds__(512)
void w1split_kernel(const float* __restrict__ W1) {
    int k = blockIdx.x;
    int n = threadIdx.x;
    float w = W1[k * D_ + n] * WSCALE;
    uint16_t h, m;
    split2(w, h, m);
    g_w1t[0][n * D_ + k] = reinterpret_cast<__half&>(h);
    g_w1t[1][n * D_ + k] = reinterpret_cast<__half&>(m);
}

// ------------------------------------------------------------------
// Kernel C: mma.sync fp16 GEMM, 3 split-products, fused gelu/W2 epilogue
// BM=128, BN=128, BK=32, 256 threads (8 warps, warp tile 64x32)
// ------------------------------------------------------------------
#define ROWB 80                    // bytes per smem row (conflict-free ldmatrix)
#define SPLIT_TILE (128 * ROWB)    // 10240 B
#define BUF_SIDE (2 * SPLIT_TILE)  // 20480 B (2 splits)
#define OFF_B (2 * BUF_SIDE)       // 40960: B tiles after A double-buffer
#define OFF_B1 (4 * BUF_SIDE)      // 81920
#define OFF_W2 (OFF_B1 + 512)
#define OFF_PART (OFF_W2 + 512)
#define SMEM_DYN (OFF_PART + 4 * 128 * 4)   // 84992
#define NCHUNK (D_ / 32)

__global__ __launch_bounds__(256, 1)
void gemm_mma_kernel(const float* __restrict__ b1, const float* __restrict__ W2,
                     const float* __restrict__ lengths)
{
    const int m0 = (blockIdx.x >> 2) * 128;
    {   // early-exit: tile fully beyond valid length of its batch row-block
        int b = m0 >> 12;
        int t0 = m0 & (L_ - 1);
        int alen = (int)(lengths[b] * (float)L_);
        if (t0 >= alen) return;
    }

    extern __shared__ char smem[];
    const uint32_t sb = smem_u32(smem);
    const int tid = threadIdx.x;
    const int wid = tid >> 5;
    const int lane = tid & 31;
    const int warp_m = wid >> 2;         // 0..1 -> 64 rows
    const int warp_n = wid & 3;          // 0..3 -> 32 cols
    const int quad = lane & 3;
    const int rowq = lane >> 2;

    const int nt = blockIdx.x & 3;
    const int n0 = nt * 128;

    float* s_b1 = (float*)(smem + OFF_B1);
    float* s_w2 = (float*)(smem + OFF_W2);
    float* s_part = (float*)(smem + OFF_PART);

    if (tid < 128) { s_b1[tid] = b1[n0 + tid]; s_w2[tid] = W2[n0 + tid]; }

    float acc[4][4][4];
#pragma unroll
    for (int i = 0; i < 4; ++i)
#pragma unroll
        for (int j = 0; j < 4; ++j)
#pragma unroll
            for (int k = 0; k < 4; ++k) acc[i][j][k] = 0.0f;

    const int l8 = lane & 7, sel = lane >> 3;
    const uint32_t a_row_off = (uint32_t)((l8 + (sel & 1) * 8) * ROWB + (sel >> 1) * 16);
    const uint32_t b_row_off = (uint32_t)((l8 + (sel >> 1) * 8) * ROWB + (sel & 1) * 16);

    auto load_chunk = [&](int c) {
        const int buf = c & 1;
        const int k0 = c * 32;
        const uint32_t da = sb + buf * BUF_SIDE;
        const uint32_t db = sb + OFF_B + buf * BUF_SIDE;
#pragma unroll
        for (int it = 0; it < 4; ++it) {
            int i = tid + it * 256;           // 0..1023
            int s = i >> 9;                   // split
            int r = (i >> 2) & 127;           // row
            int j = i & 3;                    // 16B chunk
            uint32_t doff = (uint32_t)(s * SPLIT_TILE + r * ROWB + j * 16);
            CP_ASYNC16(da + doff, &g_xs[s][(size_t)(m0 + r) * D_ + k0 + j * 8]);
            CP_ASYNC16(db + doff, &g_w1t[s][(size_t)(n0 + r) * D_ + k0 + j * 8]);
        }
        CP_COMMIT();
    };

    load_chunk(0);

    const int ca[3] = {0, 0, 1};
    const int cb[3] = {0, 1, 0};

    for (int c = 0; c < NCHUNK; ++c) {
        if (c + 1 < NCHUNK) { load_chunk(c + 1); CP_WAIT(1); }
        else { CP_WAIT(0); }
        __syncthreads();

        const int buf = c & 1;
        const uint32_t sa_base = sb + buf * BUF_SIDE + (warp_m * 64) * ROWB + a_row_off;
        const uint32_t sbb_base = sb + OFF_B + buf * BUF_SIDE + (warp_n * 32) * ROWB + b_row_off;

#pragma unroll
        for (int k16 = 0; k16 < 2; ++k16) {
            uint32_t afr[2][16], bfr[2][8];
#pragma unroll
            for (int s = 0; s < 2; ++s) {
#pragma unroll
                for (int mi = 0; mi < 4; ++mi)
                    ldsm4(&afr[s][mi * 4],
                          sa_base + (uint32_t)(s * SPLIT_TILE + mi * 16 * ROWB + k16 * 32));
#pragma unroll
                for (int nj = 0; nj < 2; ++nj)
                    ldsm4(&bfr[s][nj * 4],
                          sbb_base + (uint32_t)(s * SPLIT_TILE + nj * 16 * ROWB + k16 * 32));
            }
#pragma unroll
            for (int q = 0; q < 3; ++q) {
                const uint32_t* A = afr[ca[q]];
                const uint32_t* Bf = bfr[cb[q]];
#pragma unroll
                for (int mi = 0; mi < 4; ++mi)
#pragma unroll
                    for (int ni = 0; ni < 4; ++ni)
                        mma_f16(acc[mi][ni], &A[mi * 4],
                                &Bf[(ni >> 1) * 4 + (ni & 1) * 2]);
            }
        }
        __syncthreads();
    }

    // ---- epilogue: unscale, gelu, dot(W2) partial per row ----
#pragma unroll
    for (int mi = 0; mi < 4; ++mi) {
#pragma unroll
        for (int h = 0; h < 2; ++h) {
            float p = 0.0f;
#pragma unroll
            for (int ni = 0; ni < 4; ++ni) {
#pragma unroll
                for (int cbit = 0; cbit < 2; ++cbit) {
                    int nloc = warp_n * 32 + ni * 8 + quad * 2 + cbit;
                    float v = acc[mi][ni][h * 2 + cbit] * INV_WSCALE + s_b1[nloc];
                    float g = 0.5f * v * (1.0f + erff(v * 0.7071067811865476f));
                    p = fmaf(g, s_w2[nloc], p);
                }
            }
            p += __shfl_xor_sync(0xffffffffu, p, 1);
            p += __shfl_xor_sync(0xffffffffu, p, 2);
            if (quad == 0)
                s_part[warp_n * 128 + warp_m * 64 + mi * 16 + h * 8 + rowq] = p;
        }
    }
    __syncthreads();
    if (tid < 128) {
        float r = s_part[tid] + s_part[128 + tid] + s_part[256 + tid] + s_part[384 + tid];
        g_part[nt][m0 + tid] = r;
    }
}

// ------------------------------------------------------------------
// Kernel D: reduce partials -> probs -> boundaries -> segment table
// ------------------------------------------------------------------
__global__ __launch_bounds__(512)
void seg_kernel(const float* __restrict__ lengths,
                const float* __restrict__ b2,
                int S,
                float* __restrict__ out_masked,
                float* __restrict__ out_short,
                float* __restrict__ out_nb)
{
    const int b = blockIdx.x;
    const int tid = threadIdx.x;
    __shared__ int s_wsum[16];
    __shared__ int s_end[L_];

    const int alen = (int)(lengths[b] * (float)L_);
    int last = alen - 1;
    if (last < 0) last = 0;
    if (last > L_ - 1) last = L_ - 1;

    const float b2v = b2[0];
    const int base = tid * 8;
    int h[8];
    int loc = 0;
#pragma unroll
    for (int i = 0; i < 8; ++i) {
        int t = base + i;
        int gm = b * L_ + t;
        int valid = (t < alen) ? 1 : 0;
        float prob = 0.0f;
        int hv = 0;
        if (valid) {
            float lg = g_part[0][gm] + g_part[1][gm] + g_part[2][gm] + g_part[3][gm] + b2v;
            prob = 1.0f / (1.0f + expf(-lg));
            hv = (prob > 0.5f) ? 1 : 0;
        }
        out_masked[gm] = prob;
        if (t == last) hv = 1;
        h[i] = hv;
        loc += hv;
    }

    const int lane = tid & 31, wid = tid >> 5;
    int sc = loc;
#pragma unroll
    for (int off = 1; off < 32; off <<= 1) {
        int n = __shfl_up_sync(0xffffffffu, sc, off);
        if (lane >= off) sc += n;
    }
    if (lane == 31) s_wsum[wid] = sc;
    __syncthreads();
    if (wid == 0) {
        int w = (lane < 16) ? s_wsum[lane] : 0;
#pragma unroll
        for (int off = 1; off < 16; off <<= 1) {
            int n = __shfl_up_sync(0xffffffffu, w, off);
            if (lane >= off) w += n;
        }
        if (lane < 16) s_wsum[lane] = w;
    }
    __syncthreads();

    const int warp_off = (wid == 0) ? 0 : s_wsum[wid - 1];
    const int excl = warp_off + (sc - loc);
    const int nb = s_wsum[15];

    int run = excl;
#pragma unroll
    for (int i = 0; i < 8; ++i) {
        if (h[i]) s_end[run] = base + i;
        run += h[i];
    }
    __syncthreads();

    for (int s = tid; s < S; s += 512) {
        int st, en;
        if (s < nb) {
            en = s_end[s];
            st = (s == 0) ? 0 : (s_end[s - 1] + 1);
        } else if (s == nb) {
            st = s_end[nb - 1] + 1;   // reference quirk: invalid tail pools here
            en = L_ - 1;
        } else {
            st = 0; en = -1;
        }
        g_seg_start[b * L_ + s] = st;
        g_seg_cnt[b * L_ + s] = en - st + 1;
    }

    if (tid == 0) {
        g_nb[b] = nb;
        out_nb[b] = (float)nb;
        int sm = (S > 1) ? S : 1;
        out_short[b] = (float)nb / (float)sm;
    }
}

// ------------------------------------------------------------------
// Kernel E: segment mean-pool (skips the big tail segment)
// ------------------------------------------------------------------
__global__ __launch_bounds__(512)
void pool_kernel(const float* __restrict__ hidden, int S, float* __restrict__ out_pooled)
{
    const int s = blockIdx.x;
    const int b = blockIdx.y;
    const int nb = g_nb[b];
    if (s == nb && nb < S) return;       // handled by tail kernels

    const int tid = threadIdx.x;
    const int col = tid & 127;
    const int rg = tid >> 7;

    __shared__ float4 s_acc[512];

    const int st  = g_seg_start[b * L_ + s];
    const int cnt = g_seg_cnt[b * L_ + s];

    const float4* base = (const float4*)(hidden + (size_t)b * L_ * D_);
    float4 acc = make_float4(0.f, 0.f, 0.f, 0.f);
    for (int r = st + rg; r < st + cnt; r += 4) {
        float4 v = base[(size_t)r * (D_ / 4) + col];
        acc.x += v.x; acc.y += v.y; acc.z += v.z; acc.w += v.w;
    }
    s_acc[tid] = acc;
    __syncthreads();

    if (tid < 128) {
        float4 a = s_acc[tid], c2 = s_acc[tid + 128], c3 = s_acc[tid + 256], c4 = s_acc[tid + 384];
        a.x += c2.x + c3.x + c4.x;
        a.y += c2.y + c3.y + c4.y;
        a.z += c2.z + c3.z + c4.z;
        a.w += c2.w + c3.w + c4.w;
        float inv = 1.0f / ((float)cnt + 1e-9f);
        a.x *= inv; a.y *= inv; a.z *= inv; a.w *= inv;
        ((float4*)out_pooled)[((size_t)b * S + s) * (D_ / 4) + tid] = a;
    }
}

// ------------------------------------------------------------------
// Kernels F/G: tail segment (s == nb) split across 16 blocks + merge
// ------------------------------------------------------------------
__global__ __launch_bounds__(128)
void tail_pool_kernel(const float* __restrict__ hidden, int S)
{
    const int j = blockIdx.x;            // 0..15
    const int b = blockIdx.y;
    const int nb = g_nb[b];
    if (nb >= S) return;
    const int tid = threadIdx.x;

    const int st  = g_seg_start[b * L_ + nb];
    const int cnt = g_seg_cnt[b * L_ + nb];

    const float4* base = (const float4*)(hidden + (size_t)b * L_ * D_);
    float4 acc = make_float4(0.f, 0.f, 0.f, 0.f);
    for (int r = st + j; r < st + cnt; r += 16) {
        float4 v = base[(size_t)r * (D_ / 4) + tid];
        acc.x += v.x; acc.y += v.y; acc.z += v.z; acc.w += v.w;
    }
    ((float4*)g_tailpart[b][j])[tid] = acc;
}

__global__ __launch_bounds__(128)
void tail_merge_kernel(int S, float* __restrict__ out_pooled)
{
    const int b = blockIdx.x;
    const int nb = g_nb[b];
    if (nb >= S) return;
    const int tid = threadIdx.x;
    const int cnt = g_seg_cnt[b * L_ + nb];

    float4 a = make_float4(0.f, 0.f, 0.f, 0.f);
#pragma unroll
    for (int j = 0; j < 16; ++j) {
        float4 v = ((const float4*)g_tailpart[b][j])[tid];
        a.x += v.x; a.y += v.y; a.z += v.z; a.w += v.w;
    }
    float inv = 1.0f / ((float)cnt + 1e-9f);
    a.x *= inv; a.y *= inv; a.z *= inv; a.w *= inv;
    ((float4*)out_pooled)[((size_t)b * S + nb) * (D_ / 4) + tid] = a;
}

// ------------------------------------------------------------------
extern "C" void kernel_launch(void* const* d_in, const int* in_sizes, int n_in,
                              void* d_out, int out_size)
{
    const float* hidden  = (const float*)d_in[0];
    const float* lengths = (const float*)d_in[1];
    const float* W1      = (const float*)d_in[2];
    const float* b1      = (const float*)d_in[3];
    const float* W2      = (const float*)d_in[4];
    const float* b2      = (const float*)d_in[5];
    float* out = (float*)d_out;

    int S = (out_size - B_ * L_ - 2 * B_) / (B_ * D_);
    if (S < 1) S = 1;

    float* out_pooled = out;
    float* out_masked = out + (size_t)B_ * S * D_;
    float* out_short  = out_masked + (size_t)B_ * L_;
    float* out_nb     = out_short + B_;

    cudaFuncSetAttribute(gemm_mma_kernel, cudaFuncAttributeMaxDynamicSharedMemorySize, SMEM_DYN);

    xsplit_kernel<<<(M_TOTAL * D_ / 4) / 256, 256>>>(hidden, lengths);
    w1split_kernel<<<D_, 512>>>(W1);
    gemm_mma_kernel<<<(M_TOTAL / 128) * 4, 256, SMEM_DYN>>>(b1, W2, lengths);
    seg_kernel<<<B_, 512>>>(lengths, b2, S, out_masked, out_short, out_nb);
    pool_kernel<<<dim3(S, B_), 512>>>(hidden, S, out_pooled);
    tail_pool_kernel<<<dim3(16, B_), 128>>>(hidden, S);
    tail_merge_kernel<<<B_, 128>>>(S, out_pooled);
}